// round 5
// baseline (speedup 1.0000x reference)
#include <cuda_runtime.h>
#include <cuda_bf16.h>
#include <stdint.h>

#define N_MAX 50000
#define E_MAX 800000
#define DH 64

// ---------------- device scratch ---------------------------------------------
__device__ __align__(256) float g_bufA[N_MAX * DH];
__device__ __align__(256) float g_bufB[N_MAX * DH];
__device__ __align__(16)  float g_dis[N_MAX];
__device__ __align__(16)  int   g_cnt[N_MAX];
__device__ __align__(16)  int   g_fill[N_MAX];
__device__ __align__(16)  int   g_rowptr[N_MAX + 1];
__device__ __align__(16)  int   g_src[E_MAX];
__device__ __align__(16)  int   g_dst[E_MAX];
__device__ __align__(16)  int2  g_csr[E_MAX];          // (src, norm-as-int)
__device__ int g_is64;

// ---------------- edge dtype detect ------------------------------------------
__global__ void k_detect(const int* __restrict__ w) {
    int allz = 1;
#pragma unroll
    for (int i = 1; i < 64; i += 2) allz &= (w[i] == 0);
    g_is64 = allz;
}

// ---------------- extract + degree histogram ----------------------------------
__global__ void k_extract(const void* __restrict__ ei, int E) {
    int e = blockIdx.x * blockDim.x + threadIdx.x;
    if (e >= E) return;
    int s, d;
    if (g_is64) {
        const long long* p = (const long long*)ei;
        s = (int)p[e];
        d = (int)p[e + E];
    } else {
        const int* p = (const int*)ei;
        s = p[e];
        d = p[e + E];
    }
    g_src[e] = s;
    g_dst[e] = d;
    atomicAdd(&g_cnt[d], 1);
}

// ---------------- single-block scan: rowptr, dis, fill=0 -----------------------
__global__ __launch_bounds__(1024) void k_scan_dis(int n, int E) {
    const int T = 1024;
    int t = threadIdx.x;
    int C = (n + T - 1) / T;                 // 49
    int lo = t * C;
    int hi = lo + C < n ? lo + C : n;

    int sum = 0;
    for (int i = lo; i < hi; i++) sum += g_cnt[i];

    __shared__ int wsum[32];
    int lane = t & 31, wid = t >> 5;
    int v = sum;
#pragma unroll
    for (int o = 1; o < 32; o <<= 1) {
        int u = __shfl_up_sync(0xffffffffu, v, o);
        if (lane >= o) v += u;
    }
    if (lane == 31) wsum[wid] = v;
    __syncthreads();
    if (wid == 0) {
        int w = wsum[lane];
#pragma unroll
        for (int o = 1; o < 32; o <<= 1) {
            int u = __shfl_up_sync(0xffffffffu, w, o);
            if (lane >= o) w += u;
        }
        wsum[lane] = w;
    }
    __syncthreads();
    int run = (v - sum) + (wid > 0 ? wsum[wid - 1] : 0);   // exclusive prefix

    for (int i = lo; i < hi; i++) {
        int cv = g_cnt[i];
        g_rowptr[i] = run;
        run += cv;
        g_dis[i] = rsqrtf((float)(cv + 1));
        g_fill[i] = 0;
    }
    if (t == T - 1) g_rowptr[n] = E;
}

// ---------------- CSR fill -----------------------------------------------------
__global__ void k_fill(int E) {
    int e = blockIdx.x * blockDim.x + threadIdx.x;
    if (e >= E) return;
    int s = g_src[e];
    int d = g_dst[e];
    int pos = g_rowptr[d] + atomicAdd(&g_fill[d], 1);
    float nrm = g_dis[s] * g_dis[d];
    g_csr[pos] = make_int2(s, __float_as_int(nrm));
}

// ---------------- layer-0 GEMM: g_bufA = x @ W0 --------------------------------
__global__ __launch_bounds__(256) void k_gemm0(
    const float* __restrict__ in, const float* __restrict__ W, int n)
{
    __shared__ float Ws[64 * 64];
    int tid = threadIdx.x;
#pragma unroll
    for (int i = tid; i < 64 * 64 / 4; i += 256)
        ((float4*)Ws)[i] = ((const float4*)W)[i];
    __syncthreads();

    int node = blockIdx.x * 64 + (tid >> 2);
    int quad = tid & 3;
    if (node >= n) return;

    float acc[16];
#pragma unroll
    for (int j = 0; j < 16; j++) acc[j] = 0.f;

    const float4* xr4 = (const float4*)(in + (size_t)node * 64);
    for (int k4 = 0; k4 < 16; k4++) {
        float4 v4 = xr4[k4];
        float vv[4] = {v4.x, v4.y, v4.z, v4.w};
#pragma unroll
        for (int u = 0; u < 4; u++) {
            const float* wrow = &Ws[(k4 * 4 + u) * 64 + quad * 16];
#pragma unroll
            for (int j = 0; j < 16; j++) acc[j] = fmaf(vv[u], wrow[j], acc[j]);
        }
    }
    float* op = g_bufA + (size_t)node * 64 + quad * 16;
#pragma unroll
    for (int j = 0; j < 16; j += 4)
        *(float4*)(op + j) = make_float4(acc[j], acc[j + 1], acc[j + 2], acc[j + 3]);
}

// ---------------- fused gather + bias + relu + GEMM ----------------------------
// Phase 1: 16 threads/node gather agg[v] = dis^2*xw[v] + sum xw[src]*norm into smem.
// Phase 2: hidden: out[node, c*4..] = relu(agg+b) @ W (64x64).
//          final:  out[node, 0..8]  = relu(agg+b) @ linW + linb, k-split + shfl.
template <bool FINAL>
__global__ __launch_bounds__(256) void k_fused(
    const float* __restrict__ fin, float* __restrict__ fout,
    const float* __restrict__ W, const float* __restrict__ bias_in,
    const float* __restrict__ bias_out, int n)
{
    const int WN = FINAL ? 8 : 64;
    __shared__ float Ws[64 * WN];
    __shared__ float agg[16][68];            // row stride 68: conflict-light
    __shared__ float bs[64];
    __shared__ float lb[8];

    int tid = threadIdx.x;
#pragma unroll
    for (int i = tid; i < 64 * WN / 4; i += 256)
        ((float4*)Ws)[i] = ((const float4*)W)[i];
    if (tid < 16) ((float4*)bs)[tid] = ((const float4*)bias_in)[tid];
    if (FINAL && tid < 2) ((float4*)lb)[tid] = ((const float4*)bias_out)[tid];

    int ln = tid >> 4;
    int c  = tid & 15;
    int node = blockIdx.x * 16 + ln;
    bool ok = node < n;

    if (ok) {
        float dv = g_dis[node];
        float sl = dv * dv;
        const float4* xa = (const float4*)fin;
        float4 me = xa[node * 16 + c];
        float ax = me.x * sl, ay = me.y * sl, az = me.z * sl, aw = me.w * sl;

        int p   = g_rowptr[node];
        int end = g_rowptr[node + 1];
        for (; p + 1 < end; p += 2) {
            int2 e0 = g_csr[p];
            int2 e1 = g_csr[p + 1];
            float n0 = __int_as_float(e0.y);
            float n1 = __int_as_float(e1.y);
            float4 v0 = xa[e0.x * 16 + c];
            float4 v1 = xa[e1.x * 16 + c];
            ax = fmaf(v0.x, n0, ax); ay = fmaf(v0.y, n0, ay);
            az = fmaf(v0.z, n0, az); aw = fmaf(v0.w, n0, aw);
            ax = fmaf(v1.x, n1, ax); ay = fmaf(v1.y, n1, ay);
            az = fmaf(v1.z, n1, az); aw = fmaf(v1.w, n1, aw);
        }
        if (p < end) {
            int2 e0 = g_csr[p];
            float n0 = __int_as_float(e0.y);
            float4 v0 = xa[e0.x * 16 + c];
            ax = fmaf(v0.x, n0, ax); ay = fmaf(v0.y, n0, ay);
            az = fmaf(v0.z, n0, az); aw = fmaf(v0.w, n0, aw);
        }
        *(float4*)&agg[ln][c * 4] = make_float4(ax, ay, az, aw);
    }
    __syncthreads();

    if (!ok) return;

    if (!FINAL) {
        float acc0 = 0.f, acc1 = 0.f, acc2 = 0.f, acc3 = 0.f;
        const float* arow = agg[ln];
#pragma unroll 8
        for (int k = 0; k < 64; k++) {
            float v = fmaxf(arow[k] + bs[k], 0.f);
            const float* wr = &Ws[k * 64 + c * 4];
            acc0 = fmaf(v, wr[0], acc0);
            acc1 = fmaf(v, wr[1], acc1);
            acc2 = fmaf(v, wr[2], acc2);
            acc3 = fmaf(v, wr[3], acc3);
        }
        *(float4*)(fout + (size_t)node * 64 + c * 4) =
            make_float4(acc0, acc1, acc2, acc3);
    } else {
        float acc[8];
#pragma unroll
        for (int j = 0; j < 8; j++) acc[j] = 0.f;
        const float* arow = agg[ln];
#pragma unroll
        for (int kk = 0; kk < 4; kk++) {
            int k = c * 4 + kk;
            float v = fmaxf(arow[k] + bs[k], 0.f);
            const float* wr = &Ws[k * 8];
#pragma unroll
            for (int j = 0; j < 8; j++) acc[j] = fmaf(v, wr[j], acc[j]);
        }
#pragma unroll
        for (int o = 8; o >= 1; o >>= 1) {
#pragma unroll
            for (int j = 0; j < 8; j++)
                acc[j] += __shfl_down_sync(0xffffffffu, acc[j], o, 16);
        }
        if (c == 0) {
            float* op = fout + (size_t)node * 8;
#pragma unroll
            for (int j = 0; j < 8; j++) op[j] = acc[j] + lb[j];
        }
    }
}

// ---------------- host launcher ------------------------------------------------
extern "C" void kernel_launch(void* const* d_in, const int* in_sizes, int n_in,
                              void* d_out, int out_size)
{
    const float* x    = (const float*)d_in[0];
    const void*  ei   = d_in[1];
    const float* W0   = (const float*)d_in[2];
    const float* b0   = (const float*)d_in[3];
    const float* W1   = (const float*)d_in[4];
    const float* b1   = (const float*)d_in[5];
    const float* W2   = (const float*)d_in[6];
    const float* b2   = (const float*)d_in[7];
    const float* linW = (const float*)d_in[8];
    const float* linb = (const float*)d_in[9];
    float* out = (float*)d_out;

    int N = in_sizes[0] / DH;       // 50000
    int E = in_sizes[1] / 2;        // 800000

    const int T = 256;
    int gE = (E + T - 1) / T;       // 3125
    int gG = (N + 63) / 64;         // 782
    int gF = (N + 15) / 16;         // 3125

    // Resolve device-symbol addresses on the host (legal: pure query, no alloc).
    // Passing a __device__ array name directly as a kernel arg from host code
    // is invalid — that was the round-3 bug.
    static float* bufA = nullptr;
    static float* bufB = nullptr;
    static int*   cntP = nullptr;
    if (!bufA) {
        void* p;
        cudaGetSymbolAddress(&p, g_bufA); bufA = (float*)p;
        cudaGetSymbolAddress(&p, g_bufB); bufB = (float*)p;
        cudaGetSymbolAddress(&p, g_cnt);  cntP = (int*)p;
    }

    // zero the degree histogram (graph-capturable async memset)
    cudaMemsetAsync(cntP, 0, (size_t)N * sizeof(int));

    // CSR build (reused by all 3 layers)
    k_detect<<<1, 1>>>((const int*)ei);
    k_extract<<<gE, T>>>(ei, E);
    k_scan_dis<<<1, 1024>>>(N, E);
    k_fill<<<gE, T>>>(E);

    // layer 0 GEMM, then fused (gather_i + bias + relu + GEMM_{i+1}) chain
    k_gemm0<<<gG, T>>>(x, W0, N);
    k_fused<false><<<gF, T>>>(bufA, bufB, W1, b0, nullptr, N);
    k_fused<false><<<gF, T>>>(bufB, bufA, W2, b1, nullptr, N);
    k_fused<true ><<<gF, T>>>(bufA, out,  linW, b2, linb,   N);
}